// round 10
// baseline (speedup 1.0000x reference)
#include <cuda_runtime.h>
#include <cstdint>

#define Bc   128
#define Mc   512
#define Wc   128
#define Rc   4
#define INc  1024
#define NOUT 919
#define NPAD 960        // padded output rows (15 tiles of 64)
#define KSPL 8          // k1 split-K slices
#define DELTA 1e-6f
#define NCH  4          // k8/k9 row chunks per batch
#define CHR  128        // rows per chunk

// ---------------- scratch (device globals; no allocations) ----------------
__device__ float g_Cp[KSPL * Bc * NPAD];       // split-K partials

__device__ float g_rk[Bc * Rc * Wc];   // tanh(read keys)
__device__ float g_rs[Bc * Rc];        // softplus(read strengths)
__device__ float g_wk[Bc * Wc];        // tanh(write key)
__device__ float g_ws[Bc];             // softplus(write strength)
__device__ float g_ev[Bc * Wc];        // sigmoid(erase)
__device__ float g_wv[Bc * Wc];        // tanh(write vector)
__device__ float g_fg[Bc * Rc];        // sigmoid(free gates)
__device__ float g_ag[Bc];             // sigmoid(alloc gate)
__device__ float g_wg[Bc];             // sigmoid(write gate)
__device__ float g_rm[Bc * Rc * 3];    // raw read modes

__device__ float g_alloc[Bc * Mc];
__device__ float g_S[Bc * Mc * 16];    // per-row sums: s1,s2,s3,s4,s5,d0-3,e0-3,wdot
__device__ float g_ww  [Bc * Mc];
__device__ float g_cw  [Bc * Rc * Mc];
__device__ float g_fwd [Bc * Rc * Mc];
__device__ float g_bwdp[NCH * Bc * Rc * Mc];   // per-chunk bwd partials
__device__ float g_outp[NCH * Bc * Rc * Wc];   // per-chunk read-vector partials

// ---------------- helpers ----------------
__device__ __forceinline__ float wsum(float v) {
    v += __shfl_xor_sync(0xffffffffu, v, 16);
    v += __shfl_xor_sync(0xffffffffu, v, 8);
    v += __shfl_xor_sync(0xffffffffu, v, 4);
    v += __shfl_xor_sync(0xffffffffu, v, 2);
    v += __shfl_xor_sync(0xffffffffu, v, 1);
    return v;
}
__device__ __forceinline__ float wmaxr(float v) {
    v = fmaxf(v, __shfl_xor_sync(0xffffffffu, v, 16));
    v = fmaxf(v, __shfl_xor_sync(0xffffffffu, v, 8));
    v = fmaxf(v, __shfl_xor_sync(0xffffffffu, v, 4));
    v = fmaxf(v, __shfl_xor_sync(0xffffffffu, v, 2));
    v = fmaxf(v, __shfl_xor_sync(0xffffffffu, v, 1));
    return v;
}
__device__ __forceinline__ float pack2(float v0, float v1, int d, int lane) {
    float keep = (lane & d) ? v1 : v0;
    float send = (lane & d) ? v0 : v1;
    return keep + __shfl_xor_sync(0xffffffffu, send, d);
}
__device__ __forceinline__ float softplusf(float v) {
    return fmaxf(v, 0.f) + log1pf(expf(-fabsf(v)));
}
__device__ __forceinline__ float sigf(float v) { return 1.f / (1.f + expf(-v)); }

struct WPtrs { const float* W[10]; const float* bia[10]; };
__constant__ int c_offs[11] = {0, 512, 516, 644, 645, 773, 901, 905, 906, 907, 919};

// ---------------- K1: split-K GEMM, weights read directly from segments ----------------
__global__ __launch_bounds__(256) void k1_gemm(const float* __restrict__ A, WPtrs p) {
    __shared__ float As[32][65];
    __shared__ float Bs[32][65];
    int tx = threadIdx.x, ty = threadIdx.y;          // 16x16
    int o0 = blockIdx.x * 64, b0 = blockIdx.y * 64, kz = blockIdx.z;
    int t = ty * 16 + tx;
    int lrow = t >> 2, lc = (t & 3) * 8;             // 64 rows, 8 floats each
    int wrow = o0 + lrow;
    bool wvalid = wrow < NOUT;
    int seg = 0;
#pragma unroll
    for (int s = 0; s < 10; s++) if (wrow >= c_offs[s + 1]) seg = s + 1;
    if (!wvalid) seg = 0;
    const float* wp = p.W[seg] + (size_t)(wvalid ? (wrow - c_offs[seg]) : 0) * INc;

    float acc[4][4];
#pragma unroll
    for (int i = 0; i < 4; i++)
#pragma unroll
        for (int j = 0; j < 4; j++) acc[i][j] = 0.f;

    for (int kt = 0; kt < 4; kt++) {
        int k0 = kz * 128 + kt * 32;
        float4 a0 = *(const float4*)(A + (size_t)(b0 + lrow) * INc + k0 + lc);
        float4 a1 = *(const float4*)(A + (size_t)(b0 + lrow) * INc + k0 + lc + 4);
        float4 w0, w1;
        if (wvalid) {
            w0 = *(const float4*)(wp + k0 + lc);
            w1 = *(const float4*)(wp + k0 + lc + 4);
        } else {
            w0 = make_float4(0.f, 0.f, 0.f, 0.f);
            w1 = make_float4(0.f, 0.f, 0.f, 0.f);
        }
        if (kt) __syncthreads();
        As[lc + 0][lrow] = a0.x; As[lc + 1][lrow] = a0.y;
        As[lc + 2][lrow] = a0.z; As[lc + 3][lrow] = a0.w;
        As[lc + 4][lrow] = a1.x; As[lc + 5][lrow] = a1.y;
        As[lc + 6][lrow] = a1.z; As[lc + 7][lrow] = a1.w;
        Bs[lc + 0][lrow] = w0.x; Bs[lc + 1][lrow] = w0.y;
        Bs[lc + 2][lrow] = w0.z; Bs[lc + 3][lrow] = w0.w;
        Bs[lc + 4][lrow] = w1.x; Bs[lc + 5][lrow] = w1.y;
        Bs[lc + 6][lrow] = w1.z; Bs[lc + 7][lrow] = w1.w;
        __syncthreads();
#pragma unroll
        for (int kk = 0; kk < 32; kk++) {
            float av[4], bv[4];
#pragma unroll
            for (int i = 0; i < 4; i++) av[i] = As[kk][ty * 4 + i];
#pragma unroll
            for (int j = 0; j < 4; j++) bv[j] = Bs[kk][tx * 4 + j];
#pragma unroll
            for (int i = 0; i < 4; i++)
#pragma unroll
                for (int j = 0; j < 4; j++)
                    acc[i][j] = fmaf(av[i], bv[j], acc[i][j]);
        }
    }
#pragma unroll
    for (int i = 0; i < 4; i++) {
        float4 v = make_float4(acc[i][0], acc[i][1], acc[i][2], acc[i][3]);
        *(float4*)(g_Cp + ((size_t)kz * Bc + b0 + ty * 4 + i) * NPAD + o0 + tx * 4) = v;
    }
}

// ---------------- K1r: reduce split-K + bias + activation scatter ----------------
__global__ void k1r_act(WPtrs p) {
    int id = blockIdx.x * 256 + threadIdx.x;
    if (id >= Bc * NOUT) return;
    int b = id / NOUT, o = id % NOUT;
    float v = 0.f;
#pragma unroll
    for (int kz = 0; kz < KSPL; kz++)
        v += g_Cp[((size_t)kz * Bc + b) * NPAD + o];
    int seg = 0;
#pragma unroll
    for (int s = 0; s < 10; s++) if (o >= c_offs[s + 1]) seg = s + 1;
    v += p.bia[seg][o - c_offs[seg]];
    if      (o < 512)  g_rk[b * 512 + o]       = tanhf(v);
    else if (o < 516)  g_rs[b * 4 + o - 512]   = softplusf(v);
    else if (o < 644)  g_wk[b * 128 + o - 516] = tanhf(v);
    else if (o == 644) g_ws[b]                 = softplusf(v);
    else if (o < 773)  g_ev[b * 128 + o - 645] = sigf(v);
    else if (o < 901)  g_wv[b * 128 + o - 773] = tanhf(v);
    else if (o < 905)  g_fg[b * 4 + o - 901]   = sigf(v);
    else if (o == 905) g_ag[b]                 = sigf(v);
    else if (o == 906) g_wg[b]                 = sigf(v);
    else               g_rm[b * 12 + o - 907]  = v;
}

// ---------------- K34: heterogeneous — blocks 0..1023: memory stats; 1024..1151: alloc sort
#define K4BLKS 1024     // 8 chunks x 128 batches, 64 rows each, 512 threads
__global__ __launch_bounds__(512) void k34(const float* __restrict__ usage_v,
                                           const float* __restrict__ wwts,
                                           const float* __restrict__ rw_old,
                                           const float* __restrict__ mem) {
    __shared__ __align__(16) char raw[(3 * Wc + Rc * Wc + 14 * 512) * 4];
    int bid = blockIdx.x;
    int tid = threadIdx.x;
    int lane = tid & 31, w = tid >> 5;

    if (bid < K4BLKS) {
        // ---------- k4 role: 64 rows x 8 lanes ----------
        int b = bid >> 3, chunk = bid & 7;
        float* wk_s = (float*)raw;
        float* ev_s = wk_s + Wc;
        float* wv_s = ev_s + Wc;
        float* rk_s = wv_s + Wc;            // [Rc][Wc]
        float (*red)[512] = (float(*)[512])(rk_s + Rc * Wc);
        if (tid < Wc) {
            wk_s[tid] = g_wk[b * Wc + tid];
            ev_s[tid] = g_ev[b * Wc + tid];
            wv_s[tid] = g_wv[b * Wc + tid];
        }
        for (int e = tid; e < Rc * Wc; e += 512)          // FIX: full strided load
            rk_s[e] = g_rk[(size_t)b * Rc * Wc + e];
        __syncthreads();
        int row = chunk * 64 + (tid >> 3);
        int sl = tid & 7;
        const float* rp = mem + ((size_t)b * Mc + row) * Wc;
        float acc[14];
#pragma unroll
        for (int t = 0; t < 14; t++) acc[t] = 0.f;
#pragma unroll
        for (int q = 0; q < 4; q++) {
            int c = q * 32 + sl * 4;
            float4 v  = *(const float4*)(rp + c);
            float4 e4 = *(const float4*)(ev_s + c);
            float4 w4 = *(const float4*)(wv_s + c);
            float4 kk = *(const float4*)(wk_s + c);
            float4 ve; ve.x = v.x * e4.x; ve.y = v.y * e4.y; ve.z = v.z * e4.z; ve.w = v.w * e4.w;
            acc[0] += v.x * v.x + v.y * v.y + v.z * v.z + v.w * v.w;
            acc[1] += ve.x * v.x + ve.y * v.y + ve.z * v.z + ve.w * v.w;
            acc[2] += ve.x * ve.x + ve.y * ve.y + ve.z * ve.z + ve.w * ve.w;
            acc[3] += v.x * w4.x + v.y * w4.y + v.z * w4.z + v.w * w4.w;
            acc[4] += ve.x * w4.x + ve.y * w4.y + ve.z * w4.z + ve.w * w4.w;
#pragma unroll
            for (int r = 0; r < Rc; r++) {
                float4 k4 = *(const float4*)(rk_s + r * Wc + c);
                acc[5 + r] += v.x * k4.x + v.y * k4.y + v.z * k4.z + v.w * k4.w;
                acc[9 + r] += ve.x * k4.x + ve.y * k4.y + ve.z * k4.z + ve.w * k4.w;
            }
            acc[13] += v.x * kk.x + v.y * kk.y + v.z * kk.z + v.w * kk.w;
        }
#pragma unroll
        for (int t = 0; t < 14; t++) red[t][tid] = acc[t];
        __syncthreads();
#pragma unroll
        for (int it = 0; it < 2; it++) {
            int id = tid + it * 512;
            if (id < 64 * 14) {
                int r = id / 14, t = id - r * 14;
                const float* rr = &red[t][r * 8];
                float s = rr[0] + rr[1] + rr[2] + rr[3] + rr[4] + rr[5] + rr[6] + rr[7];
                g_S[((size_t)b * Mc + chunk * 64 + r) * 16 + t] = s;
            }
        }
        return;
    }

    // ---------- k3 role: usage + bitonic sort + allocation ----------
    int b = bid - K4BLKS;
    unsigned long long* sv = (unsigned long long*)raw;
    float* wt_ = (float*)(sv + 512);
    float* wp_ = wt_ + 16;

    float u0 = usage_v[b * Mc + tid];
    float wv = wwts[b * Mc + tid];
    float us = u0 + (1.f - u0) * wv;
    float psi = 1.f;
#pragma unroll
    for (int r = 0; r < Rc; r++)
        psi *= 1.f - g_fg[b * Rc + r] * rw_old[((size_t)b * Rc + r) * Mc + tid];
    us *= psi;
    float u = DELTA + (1.f - DELTA) * us;

    unsigned long long v = ((unsigned long long)__float_as_uint(u) << 32) | (unsigned)tid;

    for (int k = 2; k <= 512; k <<= 1) {
        for (int j = k >> 1; j >= 32; j >>= 1) {
            sv[tid] = v;
            __syncthreads();
            unsigned long long o = sv[tid ^ j];
            bool up = (tid & k) == 0;
            bool keepmin = ((tid & j) == 0) == up;
            v = (keepmin == (v < o)) ? v : o;
            __syncthreads();
        }
        int j0 = (k >> 1 < 16) ? (k >> 1) : 16;
        for (int j = j0; j >= 1; j >>= 1) {
            unsigned long long o = __shfl_xor_sync(0xffffffffu, v, j);
            bool up = (tid & k) == 0;
            bool keepmin = ((tid & j) == 0) == up;
            v = (keepmin == (v < o)) ? v : o;
        }
    }

    float su = __uint_as_float((unsigned)(v >> 32));
    float x = su;
#pragma unroll
    for (int off = 1; off < 32; off <<= 1) {
        float y = __shfl_up_sync(0xffffffffu, x, off);
        if (lane >= off) x *= y;
    }
    if (lane == 31) wt_[w] = x;
    __syncthreads();
    if (tid < 16) {
        float xx = wt_[tid];
#pragma unroll
        for (int off = 1; off < 16; off <<= 1) {
            float y = __shfl_up_sync(0xffffu, xx, off);
            if (tid >= off) xx *= y;
        }
        float ex = __shfl_up_sync(0xffffu, xx, 1);
        wp_[tid] = (tid == 0) ? 1.f : ex;
    }
    __syncthreads();
    float exw = __shfl_up_sync(0xffffffffu, x, 1);
    float excl = ((lane == 0) ? 1.f : exw) * wp_[w];
    float as = (1.f - su) * excl;
    int sidx = (int)(v & 0xffffffffu);
    g_alloc[b * Mc + sidx] = as;
}

// ---------------- K567: write weights + mem_new stats (algebraic) + read softmax ----
__global__ __launch_bounds__(512) void k567() {
    int b = blockIdx.x, tid = threadIdx.x;
    int lane = tid & 31, w = tid >> 5;
    __shared__ float part[10][4];
    __shared__ float cons[10];   // 0:Σwk² 1:Σwv² 2-5:Σwv·rk_r 6-9:Σrk_r²
    __shared__ float smax[16], ssum[16];

    if (tid < 128) {
        float wkv = g_wk[b * Wc + tid];
        float wvv = g_wv[b * Wc + tid];
        float k0 = g_rk[((size_t)b * Rc + 0) * Wc + tid];
        float k1 = g_rk[((size_t)b * Rc + 1) * Wc + tid];
        float k2 = g_rk[((size_t)b * Rc + 2) * Wc + tid];
        float k3 = g_rk[((size_t)b * Rc + 3) * Wc + tid];
        float p0 = wsum(wkv * wkv);
        float p1 = wsum(wvv * wvv);
        float p2 = wsum(wvv * k0), p3 = wsum(wvv * k1), p4 = wsum(wvv * k2), p5 = wsum(wvv * k3);
        float p6 = wsum(k0 * k0), p7 = wsum(k1 * k1), p8 = wsum(k2 * k2), p9 = wsum(k3 * k3);
        if (lane == 0) {
            part[0][w] = p0; part[1][w] = p1; part[2][w] = p2; part[3][w] = p3;
            part[4][w] = p4; part[5][w] = p5; part[6][w] = p6; part[7][w] = p7;
            part[8][w] = p8; part[9][w] = p9;
        }
    }
    __syncthreads();
    if (tid < 10) cons[tid] = part[tid][0] + part[tid][1] + part[tid][2] + part[tid][3];
    __syncthreads();

    const float* Srow = g_S + ((size_t)b * Mc + tid) * 16;
    float4 S0 = *(const float4*)(Srow);
    float4 S1 = *(const float4*)(Srow + 4);
    float4 S2 = *(const float4*)(Srow + 8);
    float4 S3 = *(const float4*)(Srow + 12);
    float s1 = S0.x, s2 = S0.y, s3 = S0.z, s4 = S0.w;
    float s5 = S1.x;
    float d0 = S1.y, d1 = S1.z, d2 = S1.w, d3 = S2.x;
    float e0 = S2.y, e1 = S2.z, e2 = S2.w, e3 = S3.x;
    float wdot = S3.y;

    float bn = sqrtf(cons[0]) + DELTA;
    float an = sqrtf(s1) + DELTA;
    float l = wdot / (128.f * bn * an + DELTA) * g_ws[b];
    float mx = wmaxr(l);
    if (lane == 0) smax[w] = mx;
    __syncthreads();
    float m2 = smax[0];
#pragma unroll
    for (int i = 1; i < 16; i++) m2 = fmaxf(m2, smax[i]);
    float e = expf(l - m2);
    float su = wsum(e);
    if (lane == 0) ssum[w] = su;
    __syncthreads();
    float tot = 0.f;
#pragma unroll
    for (int i = 0; i < 16; i++) tot += ssum[i];
    float wcw = e / tot;
    float ag = g_ag[b], wg = g_wg[b];
    float t = wg * (ag * g_alloc[b * Mc + tid] + (1.f - ag) * wcw);
    g_ww[b * Mc + tid] = t;

    float nn2 = s1 + t * (2.f * s4 - 2.f * s2) + t * t * (s3 - 2.f * s5 + cons[1]);
    float nnorm = sqrtf(fmaxf(nn2, 0.f)) + DELTA;
    float rd[4];
    rd[0] = d0 + t * (cons[2] - e0);
    rd[1] = d1 + t * (cons[3] - e1);
    rd[2] = d2 + t * (cons[4] - e2);
    rd[3] = d3 + t * (cons[5] - e3);

#pragma unroll
    for (int r = 0; r < Rc; r++) {
        float kn = sqrtf(cons[6 + r]) + DELTA;
        float lr = rd[r] / (128.f * kn * nnorm + DELTA) * g_rs[b * Rc + r];
        __syncthreads();
        float mr = wmaxr(lr);
        if (lane == 0) smax[w] = mr;
        __syncthreads();
        float mm = smax[0];
#pragma unroll
        for (int i = 1; i < 16; i++) mm = fmaxf(mm, smax[i]);
        float er = expf(lr - mm);
        float sr = wsum(er);
        if (lane == 0) ssum[w] = sr;
        __syncthreads();
        float tr = 0.f;
#pragma unroll
        for (int i = 0; i < 16; i++) tr += ssum[i];
        g_cw[((size_t)b * Rc + r) * Mc + tid] = er / tr;
    }
}

// ---------------- K8: streaming link update fused with fwd/bwd ----------------
__global__ __launch_bounds__(256) void k8_link(const float* __restrict__ link,
                                               const float* __restrict__ prec,
                                               const float* __restrict__ rw_old) {
    int c = blockIdx.x, b = blockIdx.y;
    int i0 = c * CHR;
    __shared__ float rw_s[Rc][Mc];
    __shared__ float ww_s[Mc];
    __shared__ float p_s[Mc];
    __shared__ float fwd_s[Rc][CHR];
    __shared__ float bwd_s[Rc][Mc];
    int tid = threadIdx.x;
    for (int e = tid; e < Mc; e += 256) {
        ww_s[e] = g_ww[b * Mc + e];
        p_s[e]  = prec[b * Mc + e];
    }
    for (int e = tid; e < Rc * Mc; e += 256) {
        int r = e >> 9, m = e & 511;
        rw_s[r][m] = rw_old[((size_t)b * Rc + r) * Mc + m];
        bwd_s[r][m] = 0.f;
    }
    for (int e = tid; e < Rc * CHR; e += 256) {
        int r = e >> 7, i = e & (CHR - 1);
        fwd_s[r][i] = 0.f;
    }
    __syncthreads();

    int w = tid >> 5, lane = tid & 31;
    int h = w & 3;
    int rg = w >> 2;
    int jb = h * 128 + lane * 4;

    float4 wwj = *(float4*)&ww_s[jb];
    float4 pj  = *(float4*)&p_s[jb];
    float4 rj0 = *(float4*)&rw_s[0][jb];
    float4 rj1 = *(float4*)&rw_s[1][jb];
    float4 rj2 = *(float4*)&rw_s[2][jb];
    float4 rj3 = *(float4*)&rw_s[3][jb];
    float bd0x = 0, bd0y = 0, bd0z = 0, bd0w = 0;
    float bd1x = 0, bd1y = 0, bd1z = 0, bd1w = 0;
    float bd2x = 0, bd2y = 0, bd2z = 0, bd2w = 0;
    float bd3x = 0, bd3y = 0, bd3z = 0, bd3w = 0;
    int vidx = ((lane >> 2) & 1) * 4 + ((lane >> 3) & 1) * 2 + ((lane >> 4) & 1);
    int vr = vidx & 3, vrow = vidx >> 2;

    const float* lb = link + (size_t)b * Mc * Mc;
    for (int i = i0 + rg; i < i0 + CHR; i += 4) {
        float4 xa = *(const float4*)(lb + (size_t)i * Mc + jb);
        float4 xb = *(const float4*)(lb + (size_t)(i + 2) * Mc + jb);
        float wwa = ww_s[i], wwb = ww_s[i + 2];
        float ca = 1.f - wwa, cb = 1.f - wwb;
        float A0 = fmaf(ca - wwj.x, xa.x, wwa * pj.x); if (jb     == i) A0 = 0.f;
        float A1 = fmaf(ca - wwj.y, xa.y, wwa * pj.y); if (jb + 1 == i) A1 = 0.f;
        float A2 = fmaf(ca - wwj.z, xa.z, wwa * pj.z); if (jb + 2 == i) A2 = 0.f;
        float A3 = fmaf(ca - wwj.w, xa.w, wwa * pj.w); if (jb + 3 == i) A3 = 0.f;
        float B0 = fmaf(cb - wwj.x, xb.x, wwb * pj.x); if (jb     == i + 2) B0 = 0.f;
        float B1 = fmaf(cb - wwj.y, xb.y, wwb * pj.y); if (jb + 1 == i + 2) B1 = 0.f;
        float B2 = fmaf(cb - wwj.z, xb.z, wwb * pj.z); if (jb + 2 == i + 2) B2 = 0.f;
        float B3 = fmaf(cb - wwj.w, xb.w, wwb * pj.w); if (jb + 3 == i + 2) B3 = 0.f;
        float f0 = A0 * rj0.x + A1 * rj0.y + A2 * rj0.z + A3 * rj0.w;
        float f1 = A0 * rj1.x + A1 * rj1.y + A2 * rj1.z + A3 * rj1.w;
        float f2 = A0 * rj2.x + A1 * rj2.y + A2 * rj2.z + A3 * rj2.w;
        float f3 = A0 * rj3.x + A1 * rj3.y + A2 * rj3.z + A3 * rj3.w;
        float f4 = B0 * rj0.x + B1 * rj0.y + B2 * rj0.z + B3 * rj0.w;
        float f5 = B0 * rj1.x + B1 * rj1.y + B2 * rj1.z + B3 * rj1.w;
        float f6 = B0 * rj2.x + B1 * rj2.y + B2 * rj2.z + B3 * rj2.w;
        float f7 = B0 * rj3.x + B1 * rj3.y + B2 * rj3.z + B3 * rj3.w;
        float ra0 = rw_s[0][i], ra1 = rw_s[1][i], ra2 = rw_s[2][i], ra3 = rw_s[3][i];
        float rb0 = rw_s[0][i + 2], rb1 = rw_s[1][i + 2], rb2 = rw_s[2][i + 2], rb3 = rw_s[3][i + 2];
        bd0x = fmaf(A0, ra0, fmaf(B0, rb0, bd0x)); bd0y = fmaf(A1, ra0, fmaf(B1, rb0, bd0y));
        bd0z = fmaf(A2, ra0, fmaf(B2, rb0, bd0z)); bd0w = fmaf(A3, ra0, fmaf(B3, rb0, bd0w));
        bd1x = fmaf(A0, ra1, fmaf(B0, rb1, bd1x)); bd1y = fmaf(A1, ra1, fmaf(B1, rb1, bd1y));
        bd1z = fmaf(A2, ra1, fmaf(B2, rb1, bd1z)); bd1w = fmaf(A3, ra1, fmaf(B3, rb1, bd1w));
        bd2x = fmaf(A0, ra2, fmaf(B0, rb2, bd2x)); bd2y = fmaf(A1, ra2, fmaf(B1, rb2, bd2y));
        bd2z = fmaf(A2, ra2, fmaf(B2, rb2, bd2z)); bd2w = fmaf(A3, ra2, fmaf(B3, rb2, bd2w));
        bd3x = fmaf(A0, ra3, fmaf(B0, rb3, bd3x)); bd3y = fmaf(A1, ra3, fmaf(B1, rb3, bd3y));
        bd3z = fmaf(A2, ra3, fmaf(B2, rb3, bd3z)); bd3w = fmaf(A3, ra3, fmaf(B3, rb3, bd3w));
        float pa = pack2(f0, f1, 16, lane);
        float pb = pack2(f2, f3, 16, lane);
        float pc = pack2(f4, f5, 16, lane);
        float pd = pack2(f6, f7, 16, lane);
        float qa = pack2(pa, pb, 8, lane);
        float qb = pack2(pc, pd, 8, lane);
        float g  = pack2(qa, qb, 4, lane);
        g += __shfl_xor_sync(0xffffffffu, g, 2);
        g += __shfl_xor_sync(0xffffffffu, g, 1);
        if ((lane & 3) == 0)
            atomicAdd(&fwd_s[vr][i + 2 * vrow - i0], g);
    }
    atomicAdd(&bwd_s[0][jb], bd0x); atomicAdd(&bwd_s[0][jb + 1], bd0y);
    atomicAdd(&bwd_s[0][jb + 2], bd0z); atomicAdd(&bwd_s[0][jb + 3], bd0w);
    atomicAdd(&bwd_s[1][jb], bd1x); atomicAdd(&bwd_s[1][jb + 1], bd1y);
    atomicAdd(&bwd_s[1][jb + 2], bd1z); atomicAdd(&bwd_s[1][jb + 3], bd1w);
    atomicAdd(&bwd_s[2][jb], bd2x); atomicAdd(&bwd_s[2][jb + 1], bd2y);
    atomicAdd(&bwd_s[2][jb + 2], bd2z); atomicAdd(&bwd_s[2][jb + 3], bd2w);
    atomicAdd(&bwd_s[3][jb], bd3x); atomicAdd(&bwd_s[3][jb + 1], bd3y);
    atomicAdd(&bwd_s[3][jb + 2], bd3z); atomicAdd(&bwd_s[3][jb + 3], bd3w);
    __syncthreads();
    for (int e = tid; e < Rc * CHR; e += 256) {
        int r = e >> 7, i = e & (CHR - 1);
        g_fwd[((size_t)b * Rc + r) * Mc + i0 + i] = fwd_s[r][i];
    }
    for (int e = tid; e < Rc * Mc; e += 256) {
        int r = e >> 9, m = e & 511;
        g_bwdp[(((size_t)c * Bc + b) * Rc + r) * Mc + m] = bwd_s[r][m];
    }
}

// ---------------- K9: read-mode mix + partial read vectors (chunked) ----------------
__global__ __launch_bounds__(512) void k9_out(const float* __restrict__ mem) {
    int c = blockIdx.x, b = blockIdx.y;
    int tid = threadIdx.x;
    int q = tid >> 7, wt = tid & 127;
    __shared__ float rwn[Rc][CHR];
    __shared__ float ww_s[CHR];
    __shared__ float ms[Rc][3];
    __shared__ float part[4][Rc][Wc];
    if (tid < Rc) {
        float a0 = g_rm[b * 12 + tid * 3 + 0];
        float a1 = g_rm[b * 12 + tid * 3 + 1];
        float a2 = g_rm[b * 12 + tid * 3 + 2];
        float mx = fmaxf(a0, fmaxf(a1, a2));
        float e0 = expf(a0 - mx), e1 = expf(a1 - mx), e2 = expf(a2 - mx);
        float s = e0 + e1 + e2;
        ms[tid][0] = e0 / s; ms[tid][1] = e1 / s; ms[tid][2] = e2 / s;
    }
    for (int i = tid; i < CHR; i += 512) ww_s[i] = g_ww[b * Mc + c * CHR + i];
    __syncthreads();
    for (int e = tid; e < Rc * CHR; e += 512) {
        int r = e >> 7, i = e & (CHR - 1);
        int m = c * CHR + i;
        size_t gi = ((size_t)b * Rc + r) * Mc + m;
        float bsum = 0.f;
#pragma unroll
        for (int cc = 0; cc < NCH; cc++)
            bsum += g_bwdp[(((size_t)cc * Bc + b) * Rc + r) * Mc + m];
        rwn[r][i] = ms[r][0] * bsum + ms[r][1] * g_fwd[gi] + ms[r][2] * g_cw[gi];
    }
    __syncthreads();
    float evw = g_ev[b * Wc + wt], wvw = g_wv[b * Wc + wt];
    float a0 = 0.f, a1 = 0.f, a2 = 0.f, a3 = 0.f;
    const float* mb = mem + ((size_t)b * Mc + c * CHR) * Wc;
#pragma unroll 4
    for (int i = q * 32; i < (q + 1) * 32; i++) {
        float x = mb[(size_t)i * Wc + wt];
        float t = ww_s[i];
        float nm = fmaf(x, 1.f - t * evw, t * wvw);
        a0 = fmaf(rwn[0][i], nm, a0);
        a1 = fmaf(rwn[1][i], nm, a1);
        a2 = fmaf(rwn[2][i], nm, a2);
        a3 = fmaf(rwn[3][i], nm, a3);
    }
    part[q][0][wt] = a0; part[q][1][wt] = a1; part[q][2][wt] = a2; part[q][3][wt] = a3;
    __syncthreads();
    if (q == 0) {
#pragma unroll
        for (int r = 0; r < Rc; r++)
            g_outp[(((size_t)c * Bc + b) * Rc + r) * Wc + wt] =
                part[0][r][wt] + part[1][r][wt] + part[2][r][wt] + part[3][r][wt];
    }
}

// ---------------- K10: reduce chunk partials ----------------
__global__ void k10_reduce(float* __restrict__ out) {
    int id = blockIdx.x * 256 + threadIdx.x;
    if (id >= Bc * Rc * Wc) return;
    float s = 0.f;
#pragma unroll
    for (int c = 0; c < NCH; c++)
        s += g_outp[(size_t)c * Bc * Rc * Wc + id];
    out[id] = s;
}

// ---------------- launch ----------------
extern "C" void kernel_launch(void* const* d_in, const int* in_sizes, int n_in,
                              void* d_out, int out_size) {
    const float* x        = (const float*)d_in[0];
    const float* memory   = (const float*)d_in[1];
    const float* link     = (const float*)d_in[2];
    const float* prec     = (const float*)d_in[3];
    const float* rw_old   = (const float*)d_in[4];
    const float* wwts     = (const float*)d_in[5];
    const float* usage_v  = (const float*)d_in[6];

    WPtrs p;
    for (int s = 0; s < 10; s++) {
        p.W[s]   = (const float*)d_in[7 + 2 * s];
        p.bia[s] = (const float*)d_in[8 + 2 * s];
    }
    float* out = (float*)d_out;

    k1_gemm<<<dim3(NPAD / 64, Bc / 64, KSPL), dim3(16, 16)>>>(x, p);
    k1r_act<<<(Bc * NOUT + 255) / 256, 256>>>(p);
    k34<<<K4BLKS + Bc, 512>>>(usage_v, wwts, rw_old, memory);
    k567<<<Bc, 512>>>();
    k8_link<<<dim3(NCH, Bc), 256>>>(link, prec, rw_old);
    k9_out<<<dim3(NCH, Bc), 512>>>(memory);
    k10_reduce<<<(Bc * Rc * Wc + 255) / 256, 256>>>(out);
}

// round 11
// speedup vs baseline: 1.1656x; 1.1656x over previous
#include <cuda_runtime.h>
#include <cstdint>

#define Bc   128
#define Mc   512
#define Wc   128
#define Rc   4
#define INc  1024
#define NOUT 919
#define NPAD 960
#define KSPL 8
#define DELTA 1e-6f
#define NCH  4
#define CHR  128

// ---------------- scratch (device globals; no allocations) ----------------
__device__ float g_Cp[KSPL * Bc * NPAD];

__device__ float g_rk[Bc * Rc * Wc];
__device__ float g_rs[Bc * Rc];
__device__ float g_wk[Bc * Wc];
__device__ float g_ws[Bc];
__device__ float g_ev[Bc * Wc];
__device__ float g_wv[Bc * Wc];
__device__ float g_fg[Bc * Rc];
__device__ float g_ag[Bc];
__device__ float g_wg[Bc];
__device__ float g_rm[Bc * Rc * 3];

__device__ float g_alloc[Bc * Mc];
__device__ float g_S[Bc * Mc * 16];
__device__ float g_ww  [Bc * Mc];
__device__ float g_cw  [Bc * Rc * Mc];
__device__ float g_fwd [Bc * Rc * Mc];
__device__ float g_bwdp[NCH * Bc * Rc * Mc];
__device__ float g_outp[NCH * Bc * Rc * Wc];

// ---------------- helpers ----------------
__device__ __forceinline__ float wsum(float v) {
    v += __shfl_xor_sync(0xffffffffu, v, 16);
    v += __shfl_xor_sync(0xffffffffu, v, 8);
    v += __shfl_xor_sync(0xffffffffu, v, 4);
    v += __shfl_xor_sync(0xffffffffu, v, 2);
    v += __shfl_xor_sync(0xffffffffu, v, 1);
    return v;
}
__device__ __forceinline__ float wmaxr(float v) {
    v = fmaxf(v, __shfl_xor_sync(0xffffffffu, v, 16));
    v = fmaxf(v, __shfl_xor_sync(0xffffffffu, v, 8));
    v = fmaxf(v, __shfl_xor_sync(0xffffffffu, v, 4));
    v = fmaxf(v, __shfl_xor_sync(0xffffffffu, v, 2));
    v = fmaxf(v, __shfl_xor_sync(0xffffffffu, v, 1));
    return v;
}
__device__ __forceinline__ float pack2(float v0, float v1, int d, int lane) {
    float keep = (lane & d) ? v1 : v0;
    float send = (lane & d) ? v0 : v1;
    return keep + __shfl_xor_sync(0xffffffffu, send, d);
}
__device__ __forceinline__ float pmax2(float v0, float v1, int d, int lane) {
    float keep = (lane & d) ? v1 : v0;
    float send = (lane & d) ? v0 : v1;
    return fmaxf(keep, __shfl_xor_sync(0xffffffffu, send, d));
}
__device__ __forceinline__ float softplusf(float v) {
    return fmaxf(v, 0.f) + log1pf(expf(-fabsf(v)));
}
__device__ __forceinline__ float sigf(float v) { return 1.f / (1.f + expf(-v)); }

struct WPtrs { const float* W[10]; const float* bia[10]; };
__constant__ int c_offs[11] = {0, 512, 516, 644, 645, 773, 901, 905, 906, 907, 919};

// ---------------- K1: split-K GEMM, weights read directly from segments ----------------
__global__ __launch_bounds__(256) void k1_gemm(const float* __restrict__ A, WPtrs p) {
    __shared__ float As[32][65];
    __shared__ float Bs[32][65];
    int tx = threadIdx.x, ty = threadIdx.y;
    int o0 = blockIdx.x * 64, b0 = blockIdx.y * 64, kz = blockIdx.z;
    int t = ty * 16 + tx;
    int lrow = t >> 2, lc = (t & 3) * 8;
    int wrow = o0 + lrow;
    bool wvalid = wrow < NOUT;
    int seg = 0;
#pragma unroll
    for (int s = 0; s < 10; s++) if (wrow >= c_offs[s + 1]) seg = s + 1;
    if (!wvalid) seg = 0;
    const float* wp = p.W[seg] + (size_t)(wvalid ? (wrow - c_offs[seg]) : 0) * INc;

    float acc[4][4];
#pragma unroll
    for (int i = 0; i < 4; i++)
#pragma unroll
        for (int j = 0; j < 4; j++) acc[i][j] = 0.f;

    for (int kt = 0; kt < 4; kt++) {
        int k0 = kz * 128 + kt * 32;
        float4 a0 = *(const float4*)(A + (size_t)(b0 + lrow) * INc + k0 + lc);
        float4 a1 = *(const float4*)(A + (size_t)(b0 + lrow) * INc + k0 + lc + 4);
        float4 w0, w1;
        if (wvalid) {
            w0 = *(const float4*)(wp + k0 + lc);
            w1 = *(const float4*)(wp + k0 + lc + 4);
        } else {
            w0 = make_float4(0.f, 0.f, 0.f, 0.f);
            w1 = make_float4(0.f, 0.f, 0.f, 0.f);
        }
        if (kt) __syncthreads();
        As[lc + 0][lrow] = a0.x; As[lc + 1][lrow] = a0.y;
        As[lc + 2][lrow] = a0.z; As[lc + 3][lrow] = a0.w;
        As[lc + 4][lrow] = a1.x; As[lc + 5][lrow] = a1.y;
        As[lc + 6][lrow] = a1.z; As[lc + 7][lrow] = a1.w;
        Bs[lc + 0][lrow] = w0.x; Bs[lc + 1][lrow] = w0.y;
        Bs[lc + 2][lrow] = w0.z; Bs[lc + 3][lrow] = w0.w;
        Bs[lc + 4][lrow] = w1.x; Bs[lc + 5][lrow] = w1.y;
        Bs[lc + 6][lrow] = w1.z; Bs[lc + 7][lrow] = w1.w;
        __syncthreads();
#pragma unroll
        for (int kk = 0; kk < 32; kk++) {
            float av[4], bv[4];
#pragma unroll
            for (int i = 0; i < 4; i++) av[i] = As[kk][ty * 4 + i];
#pragma unroll
            for (int j = 0; j < 4; j++) bv[j] = Bs[kk][tx * 4 + j];
#pragma unroll
            for (int i = 0; i < 4; i++)
#pragma unroll
                for (int j = 0; j < 4; j++)
                    acc[i][j] = fmaf(av[i], bv[j], acc[i][j]);
        }
    }
#pragma unroll
    for (int i = 0; i < 4; i++) {
        float4 v = make_float4(acc[i][0], acc[i][1], acc[i][2], acc[i][3]);
        *(float4*)(g_Cp + ((size_t)kz * Bc + b0 + ty * 4 + i) * NPAD + o0 + tx * 4) = v;
    }
}

// ---------------- K1r: reduce split-K + bias + activation scatter ----------------
__global__ void k1r_act(WPtrs p) {
    int id = blockIdx.x * 256 + threadIdx.x;
    if (id >= Bc * NOUT) return;
    int b = id / NOUT, o = id % NOUT;
    float v = 0.f;
#pragma unroll
    for (int kz = 0; kz < KSPL; kz++)
        v += g_Cp[((size_t)kz * Bc + b) * NPAD + o];
    int seg = 0;
#pragma unroll
    for (int s = 0; s < 10; s++) if (o >= c_offs[s + 1]) seg = s + 1;
    v += p.bia[seg][o - c_offs[seg]];
    if      (o < 512)  g_rk[b * 512 + o]       = tanhf(v);
    else if (o < 516)  g_rs[b * 4 + o - 512]   = softplusf(v);
    else if (o < 644)  g_wk[b * 128 + o - 516] = tanhf(v);
    else if (o == 644) g_ws[b]                 = softplusf(v);
    else if (o < 773)  g_ev[b * 128 + o - 645] = sigf(v);
    else if (o < 901)  g_wv[b * 128 + o - 773] = tanhf(v);
    else if (o < 905)  g_fg[b * 4 + o - 901]   = sigf(v);
    else if (o == 905) g_ag[b]                 = sigf(v);
    else if (o == 906) g_wg[b]                 = sigf(v);
    else               g_rm[b * 12 + o - 907]  = v;
}

// ---------------- K34: heterogeneous — blocks 0..1023: memory stats; 1024..1151: alloc sort
#define K4BLKS 1024
__global__ __launch_bounds__(512) void k34(const float* __restrict__ usage_v,
                                           const float* __restrict__ wwts,
                                           const float* __restrict__ rw_old,
                                           const float* __restrict__ mem) {
    __shared__ __align__(16) char raw[(3 * Wc + Rc * Wc + 14 * 512) * 4];
    int bid = blockIdx.x;
    int tid = threadIdx.x;
    int lane = tid & 31, w = tid >> 5;

    if (bid < K4BLKS) {
        int b = bid >> 3, chunk = bid & 7;
        float* wk_s = (float*)raw;
        float* ev_s = wk_s + Wc;
        float* wv_s = ev_s + Wc;
        float* rk_s = wv_s + Wc;
        float (*red)[512] = (float(*)[512])(rk_s + Rc * Wc);
        if (tid < Wc) {
            wk_s[tid] = g_wk[b * Wc + tid];
            ev_s[tid] = g_ev[b * Wc + tid];
            wv_s[tid] = g_wv[b * Wc + tid];
        }
        for (int e = tid; e < Rc * Wc; e += 512)
            rk_s[e] = g_rk[(size_t)b * Rc * Wc + e];
        __syncthreads();
        int row = chunk * 64 + (tid >> 3);
        int sl = tid & 7;
        const float* rp = mem + ((size_t)b * Mc + row) * Wc;
        float acc[14];
#pragma unroll
        for (int t = 0; t < 14; t++) acc[t] = 0.f;
#pragma unroll
        for (int q = 0; q < 4; q++) {
            int c = q * 32 + sl * 4;
            float4 v  = *(const float4*)(rp + c);
            float4 e4 = *(const float4*)(ev_s + c);
            float4 w4 = *(const float4*)(wv_s + c);
            float4 kk = *(const float4*)(wk_s + c);
            float4 ve; ve.x = v.x * e4.x; ve.y = v.y * e4.y; ve.z = v.z * e4.z; ve.w = v.w * e4.w;
            acc[0] += v.x * v.x + v.y * v.y + v.z * v.z + v.w * v.w;
            acc[1] += ve.x * v.x + ve.y * v.y + ve.z * v.z + ve.w * v.w;
            acc[2] += ve.x * ve.x + ve.y * ve.y + ve.z * ve.z + ve.w * ve.w;
            acc[3] += v.x * w4.x + v.y * w4.y + v.z * w4.z + v.w * w4.w;
            acc[4] += ve.x * w4.x + ve.y * w4.y + ve.z * w4.z + ve.w * w4.w;
#pragma unroll
            for (int r = 0; r < Rc; r++) {
                float4 k4 = *(const float4*)(rk_s + r * Wc + c);
                acc[5 + r] += v.x * k4.x + v.y * k4.y + v.z * k4.z + v.w * k4.w;
                acc[9 + r] += ve.x * k4.x + ve.y * k4.y + ve.z * k4.z + ve.w * k4.w;
            }
            acc[13] += v.x * kk.x + v.y * kk.y + v.z * kk.z + v.w * kk.w;
        }
#pragma unroll
        for (int t = 0; t < 14; t++) red[t][tid] = acc[t];
        __syncthreads();
#pragma unroll
        for (int it = 0; it < 2; it++) {
            int id = tid + it * 512;
            if (id < 64 * 14) {
                int r = id / 14, t = id - r * 14;
                const float* rr = &red[t][r * 8];
                float s = rr[0] + rr[1] + rr[2] + rr[3] + rr[4] + rr[5] + rr[6] + rr[7];
                g_S[((size_t)b * Mc + chunk * 64 + r) * 16 + t] = s;
            }
        }
        return;
    }

    // ---------- k3 role ----------
    int b = bid - K4BLKS;
    unsigned long long* sv = (unsigned long long*)raw;
    float* wt_ = (float*)(sv + 512);
    float* wp_ = wt_ + 16;

    float u0 = usage_v[b * Mc + tid];
    float wv = wwts[b * Mc + tid];
    float us = u0 + (1.f - u0) * wv;
    float psi = 1.f;
#pragma unroll
    for (int r = 0; r < Rc; r++)
        psi *= 1.f - g_fg[b * Rc + r] * rw_old[((size_t)b * Rc + r) * Mc + tid];
    us *= psi;
    float u = DELTA + (1.f - DELTA) * us;

    unsigned long long v = ((unsigned long long)__float_as_uint(u) << 32) | (unsigned)tid;

    for (int k = 2; k <= 512; k <<= 1) {
        for (int j = k >> 1; j >= 32; j >>= 1) {
            sv[tid] = v;
            __syncthreads();
            unsigned long long o = sv[tid ^ j];
            bool up = (tid & k) == 0;
            bool keepmin = ((tid & j) == 0) == up;
            v = (keepmin == (v < o)) ? v : o;
            __syncthreads();
        }
        int j0 = (k >> 1 < 16) ? (k >> 1) : 16;
        for (int j = j0; j >= 1; j >>= 1) {
            unsigned long long o = __shfl_xor_sync(0xffffffffu, v, j);
            bool up = (tid & k) == 0;
            bool keepmin = ((tid & j) == 0) == up;
            v = (keepmin == (v < o)) ? v : o;
        }
    }

    float su = __uint_as_float((unsigned)(v >> 32));
    float x = su;
#pragma unroll
    for (int off = 1; off < 32; off <<= 1) {
        float y = __shfl_up_sync(0xffffffffu, x, off);
        if (lane >= off) x *= y;
    }
    if (lane == 31) wt_[w] = x;
    __syncthreads();
    if (tid < 16) {
        float xx = wt_[tid];
#pragma unroll
        for (int off = 1; off < 16; off <<= 1) {
            float y = __shfl_up_sync(0xffffu, xx, off);
            if (tid >= off) xx *= y;
        }
        float ex = __shfl_up_sync(0xffffu, xx, 1);
        wp_[tid] = (tid == 0) ? 1.f : ex;
    }
    __syncthreads();
    float exw = __shfl_up_sync(0xffffffffu, x, 1);
    float excl = ((lane == 0) ? 1.f : exw) * wp_[w];
    float as = (1.f - su) * excl;
    int sidx = (int)(v & 0xffffffffu);
    g_alloc[b * Mc + sidx] = as;
}

// ---------------- K567: write weights + mem_new stats + packed read softmaxes ----
__global__ __launch_bounds__(512) void k567() {
    int b = blockIdx.x, tid = threadIdx.x;
    int lane = tid & 31, w = tid >> 5;
    __shared__ float part[10][4];
    __shared__ float cons[10];
    __shared__ float smax[16], ssum[16];
    __shared__ float smax4[Rc][16], ssum4[Rc][16];

    if (tid < 128) {
        float wkv = g_wk[b * Wc + tid];
        float wvv = g_wv[b * Wc + tid];
        float k0 = g_rk[((size_t)b * Rc + 0) * Wc + tid];
        float k1 = g_rk[((size_t)b * Rc + 1) * Wc + tid];
        float k2 = g_rk[((size_t)b * Rc + 2) * Wc + tid];
        float k3 = g_rk[((size_t)b * Rc + 3) * Wc + tid];
        float p0 = wsum(wkv * wkv);
        float p1 = wsum(wvv * wvv);
        float p2 = wsum(wvv * k0), p3 = wsum(wvv * k1), p4 = wsum(wvv * k2), p5 = wsum(wvv * k3);
        float p6 = wsum(k0 * k0), p7 = wsum(k1 * k1), p8 = wsum(k2 * k2), p9 = wsum(k3 * k3);
        if (lane == 0) {
            part[0][w] = p0; part[1][w] = p1; part[2][w] = p2; part[3][w] = p3;
            part[4][w] = p4; part[5][w] = p5; part[6][w] = p6; part[7][w] = p7;
            part[8][w] = p8; part[9][w] = p9;
        }
    }
    __syncthreads();
    if (tid < 10) cons[tid] = part[tid][0] + part[tid][1] + part[tid][2] + part[tid][3];
    __syncthreads();

    const float* Srow = g_S + ((size_t)b * Mc + tid) * 16;
    float4 S0 = *(const float4*)(Srow);
    float4 S1 = *(const float4*)(Srow + 4);
    float4 S2 = *(const float4*)(Srow + 8);
    float4 S3 = *(const float4*)(Srow + 12);
    float s1 = S0.x, s2 = S0.y, s3 = S0.z, s4 = S0.w;
    float s5 = S1.x;
    float d0 = S1.y, d1 = S1.z, d2 = S1.w, d3 = S2.x;
    float e0 = S2.y, e1 = S2.z, e2 = S2.w, e3 = S3.x;
    float wdot = S3.y;

    // write content softmax + write weights
    float bn = sqrtf(cons[0]) + DELTA;
    float an = sqrtf(s1) + DELTA;
    float l = wdot / (128.f * bn * an + DELTA) * g_ws[b];
    float mx = wmaxr(l);
    if (lane == 0) smax[w] = mx;
    __syncthreads();
    float m2 = smax[0];
#pragma unroll
    for (int i = 1; i < 16; i++) m2 = fmaxf(m2, smax[i]);
    float e = expf(l - m2);
    float su = wsum(e);
    if (lane == 0) ssum[w] = su;
    __syncthreads();
    float tot = 0.f;
#pragma unroll
    for (int i = 0; i < 16; i++) tot += ssum[i];
    float wcw = e / tot;
    float ag = g_ag[b], wg = g_wg[b];
    float t = wg * (ag * g_alloc[b * Mc + tid] + (1.f - ag) * wcw);
    g_ww[b * Mc + tid] = t;

    // mem_new stats (algebraic)
    float nn2 = s1 + t * (2.f * s4 - 2.f * s2) + t * t * (s3 - 2.f * s5 + cons[1]);
    float nnorm = sqrtf(fmaxf(nn2, 0.f)) + DELTA;
    float lr[4];
    lr[0] = (d0 + t * (cons[2] - e0)) / (128.f * (sqrtf(cons[6]) + DELTA) * nnorm + DELTA) * g_rs[b * Rc + 0];
    lr[1] = (d1 + t * (cons[3] - e1)) / (128.f * (sqrtf(cons[7]) + DELTA) * nnorm + DELTA) * g_rs[b * Rc + 1];
    lr[2] = (d2 + t * (cons[4] - e2)) / (128.f * (sqrtf(cons[8]) + DELTA) * nnorm + DELTA) * g_rs[b * Rc + 2];
    lr[3] = (d3 + t * (cons[5] - e3)) / (128.f * (sqrtf(cons[9]) + DELTA) * nnorm + DELTA) * g_rs[b * Rc + 3];

    // packed 4-softmax: r held by lane = bit16 + 2*bit8
    int rsel = ((lane >> 4) & 1) | (((lane >> 3) & 1) << 1);
    {
        float pa = pmax2(lr[0], lr[1], 16, lane);
        float pb = pmax2(lr[2], lr[3], 16, lane);
        float q  = pmax2(pa, pb, 8, lane);
        q = fmaxf(q, __shfl_xor_sync(0xffffffffu, q, 4));
        q = fmaxf(q, __shfl_xor_sync(0xffffffffu, q, 2));
        q = fmaxf(q, __shfl_xor_sync(0xffffffffu, q, 1));
        if ((lane & 7) == 0) smax4[rsel][w] = q;
    }
    __syncthreads();
    float er[4];
#pragma unroll
    for (int r = 0; r < Rc; r++) {
        float mm = smax4[r][0];
#pragma unroll
        for (int i = 1; i < 16; i++) mm = fmaxf(mm, smax4[r][i]);
        er[r] = expf(lr[r] - mm);
    }
    {
        float pa = pack2(er[0], er[1], 16, lane);
        float pb = pack2(er[2], er[3], 16, lane);
        float q  = pack2(pa, pb, 8, lane);
        q += __shfl_xor_sync(0xffffffffu, q, 4);
        q += __shfl_xor_sync(0xffffffffu, q, 2);
        q += __shfl_xor_sync(0xffffffffu, q, 1);
        if ((lane & 7) == 0) ssum4[rsel][w] = q;
    }
    __syncthreads();
#pragma unroll
    for (int r = 0; r < Rc; r++) {
        float tr = 0.f;
#pragma unroll
        for (int i = 0; i < 16; i++) tr += ssum4[r][i];
        g_cw[((size_t)b * Rc + r) * Mc + tid] = er[r] / tr;
    }
}

// ---------------- K8: streaming link update fused with fwd/bwd (121.3µs version) ----
__global__ __launch_bounds__(256) void k8_link(const float* __restrict__ link,
                                               const float* __restrict__ prec,
                                               const float* __restrict__ rw_old) {
    int c = blockIdx.x, b = blockIdx.y;
    int i0 = c * CHR;
    __shared__ float rw_s[Rc][Mc];
    __shared__ float ww_s[Mc];
    __shared__ float p_s[Mc];
    __shared__ float fwd_s[Rc][CHR];
    __shared__ float bwd_s[Rc][Mc];
    int tid = threadIdx.x;
    for (int e = tid; e < Mc; e += 256) {
        ww_s[e] = g_ww[b * Mc + e];
        p_s[e]  = prec[b * Mc + e];
    }
    for (int e = tid; e < Rc * Mc; e += 256) {
        int r = e >> 9, m = e & 511;
        rw_s[r][m] = rw_old[((size_t)b * Rc + r) * Mc + m];
        bwd_s[r][m] = 0.f;
    }
    for (int e = tid; e < Rc * CHR; e += 256) {
        int r = e >> 7, i = e & (CHR - 1);
        fwd_s[r][i] = 0.f;
    }
    __syncthreads();

    int w = tid >> 5, lane = tid & 31;
    int h = w & 3;
    int rg = w >> 2;
    int jb = h * 128 + lane * 4;

    float4 wwj = *(float4*)&ww_s[jb];
    float4 pj  = *(float4*)&p_s[jb];
    float4 rj0 = *(float4*)&rw_s[0][jb];
    float4 rj1 = *(float4*)&rw_s[1][jb];
    float4 rj2 = *(float4*)&rw_s[2][jb];
    float4 rj3 = *(float4*)&rw_s[3][jb];
    float bd0x = 0, bd0y = 0, bd0z = 0, bd0w = 0;
    float bd1x = 0, bd1y = 0, bd1z = 0, bd1w = 0;
    float bd2x = 0, bd2y = 0, bd2z = 0, bd2w = 0;
    float bd3x = 0, bd3y = 0, bd3z = 0, bd3w = 0;
    int ridx = ((lane >> 4) & 1) | ((lane >> 2) & 2);

    const float* lb = link + (size_t)b * Mc * Mc;
    float4 x = *(const float4*)(lb + (size_t)(i0 + rg) * Mc + jb);
    for (int i = i0 + rg; i < i0 + CHR; i += 2) {
        float4 xn = x;
        if (i + 2 < i0 + CHR)
            xn = *(const float4*)(lb + (size_t)(i + 2) * Mc + jb);
        float wwi = ww_s[i];
        float c1 = 1.f - wwi;
        float T0 = fmaf(c1 - wwj.x, x.x, wwi * pj.x); if (jb     == i) T0 = 0.f;
        float T1 = fmaf(c1 - wwj.y, x.y, wwi * pj.y); if (jb + 1 == i) T1 = 0.f;
        float T2 = fmaf(c1 - wwj.z, x.z, wwi * pj.z); if (jb + 2 == i) T2 = 0.f;
        float T3 = fmaf(c1 - wwj.w, x.w, wwi * pj.w); if (jb + 3 == i) T3 = 0.f;
        float f0 = T0 * rj0.x + T1 * rj0.y + T2 * rj0.z + T3 * rj0.w;
        float f1 = T0 * rj1.x + T1 * rj1.y + T2 * rj1.z + T3 * rj1.w;
        float f2 = T0 * rj2.x + T1 * rj2.y + T2 * rj2.z + T3 * rj2.w;
        float f3 = T0 * rj3.x + T1 * rj3.y + T2 * rj3.z + T3 * rj3.w;
        float ri0 = rw_s[0][i], ri1 = rw_s[1][i], ri2 = rw_s[2][i], ri3 = rw_s[3][i];
        bd0x = fmaf(T0, ri0, bd0x); bd0y = fmaf(T1, ri0, bd0y); bd0z = fmaf(T2, ri0, bd0z); bd0w = fmaf(T3, ri0, bd0w);
        bd1x = fmaf(T0, ri1, bd1x); bd1y = fmaf(T1, ri1, bd1y); bd1z = fmaf(T2, ri1, bd1z); bd1w = fmaf(T3, ri1, bd1w);
        bd2x = fmaf(T0, ri2, bd2x); bd2y = fmaf(T1, ri2, bd2y); bd2z = fmaf(T2, ri2, bd2z); bd2w = fmaf(T3, ri2, bd2w);
        bd3x = fmaf(T0, ri3, bd3x); bd3y = fmaf(T1, ri3, bd3y); bd3z = fmaf(T2, ri3, bd3z); bd3w = fmaf(T3, ri3, bd3w);
        float a  = pack2(f0, f1, 16, lane);
        float c2 = pack2(f2, f3, 16, lane);
        float v  = pack2(a, c2, 8, lane);
        v += __shfl_xor_sync(0xffffffffu, v, 4);
        v += __shfl_xor_sync(0xffffffffu, v, 2);
        v += __shfl_xor_sync(0xffffffffu, v, 1);
        if ((lane & 7) == 0) atomicAdd(&fwd_s[ridx][i - i0], v);
        x = xn;
    }
    atomicAdd(&bwd_s[0][jb], bd0x); atomicAdd(&bwd_s[0][jb + 1], bd0y);
    atomicAdd(&bwd_s[0][jb + 2], bd0z); atomicAdd(&bwd_s[0][jb + 3], bd0w);
    atomicAdd(&bwd_s[1][jb], bd1x); atomicAdd(&bwd_s[1][jb + 1], bd1y);
    atomicAdd(&bwd_s[1][jb + 2], bd1z); atomicAdd(&bwd_s[1][jb + 3], bd1w);
    atomicAdd(&bwd_s[2][jb], bd2x); atomicAdd(&bwd_s[2][jb + 1], bd2y);
    atomicAdd(&bwd_s[2][jb + 2], bd2z); atomicAdd(&bwd_s[2][jb + 3], bd2w);
    atomicAdd(&bwd_s[3][jb], bd3x); atomicAdd(&bwd_s[3][jb + 1], bd3y);
    atomicAdd(&bwd_s[3][jb + 2], bd3z); atomicAdd(&bwd_s[3][jb + 3], bd3w);
    __syncthreads();
    for (int e = tid; e < Rc * CHR; e += 256) {
        int r = e >> 7, i = e & (CHR - 1);
        g_fwd[((size_t)b * Rc + r) * Mc + i0 + i] = fwd_s[r][i];
    }
    for (int e = tid; e < Rc * Mc; e += 256) {
        int r = e >> 9, m = e & 511;
        g_bwdp[(((size_t)c * Bc + b) * Rc + r) * Mc + m] = bwd_s[r][m];
    }
}

// ---------------- K9: read-mode mix + partial read vectors (chunked) ----------------
__global__ __launch_bounds__(512) void k9_out(const float* __restrict__ mem) {
    int c = blockIdx.x, b = blockIdx.y;
    int tid = threadIdx.x;
    int q = tid >> 7, wt = tid & 127;
    __shared__ float rwn[Rc][CHR];
    __shared__ float ww_s[CHR];
    __shared__ float ms[Rc][3];
    __shared__ float part[4][Rc][Wc];
    if (tid < Rc) {
        float a0 = g_rm[b * 12 + tid * 3 + 0];
        float a1 = g_rm[b * 12 + tid * 3 + 1];
        float a2 = g_rm[b * 12 + tid * 3 + 2];
        float mx = fmaxf(a0, fmaxf(a1, a2));
        float e0 = expf(a0 - mx), e1 = expf(a1 - mx), e2 = expf(a2 - mx);
        float s = e0 + e1 + e2;
        ms[tid][0] = e0 / s; ms[tid][1] = e1 / s; ms[tid][2] = e2 / s;
    }
    for (int i = tid; i < CHR; i += 512) ww_s[i] = g_ww[b * Mc + c * CHR + i];
    __syncthreads();
    for (int e = tid; e < Rc * CHR; e += 512) {
        int r = e >> 7, i = e & (CHR - 1);
        int m = c * CHR + i;
        size_t gi = ((size_t)b * Rc + r) * Mc + m;
        float bsum = 0.f;
#pragma unroll
        for (int cc = 0; cc < NCH; cc++)
            bsum += g_bwdp[(((size_t)cc * Bc + b) * Rc + r) * Mc + m];
        rwn[r][i] = ms[r][0] * bsum + ms[r][1] * g_fwd[gi] + ms[r][2] * g_cw[gi];
    }
    __syncthreads();
    float evw = g_ev[b * Wc + wt], wvw = g_wv[b * Wc + wt];
    float a0 = 0.f, a1 = 0.f, a2 = 0.f, a3 = 0.f;
    const float* mb = mem + ((size_t)b * Mc + c * CHR) * Wc;
#pragma unroll 4
    for (int i = q * 32; i < (q + 1) * 32; i++) {
        float x = mb[(size_t)i * Wc + wt];
        float t = ww_s[i];
        float nm = fmaf(x, 1.f - t * evw, t * wvw);
        a0 = fmaf(rwn[0][i], nm, a0);
        a1 = fmaf(rwn[1][i], nm, a1);
        a2 = fmaf(rwn[2][i], nm, a2);
        a3 = fmaf(rwn[3][i], nm, a3);
    }
    part[q][0][wt] = a0; part[q][1][wt] = a1; part[q][2][wt] = a2; part[q][3][wt] = a3;
    __syncthreads();
    if (q == 0) {
#pragma unroll
        for (int r = 0; r < Rc; r++)
            g_outp[(((size_t)c * Bc + b) * Rc + r) * Wc + wt] =
                part[0][r][wt] + part[1][r][wt] + part[2][r][wt] + part[3][r][wt];
    }
}

// ---------------- K10: reduce chunk partials ----------------
__global__ void k10_reduce(float* __restrict__ out) {
    int id = blockIdx.x * 256 + threadIdx.x;
    if (id >= Bc * Rc * Wc) return;
    float s = 0.f;
#pragma unroll
    for (int c = 0; c < NCH; c++)
        s += g_outp[(size_t)c * Bc * Rc * Wc + id];
    out[id] = s;
}

// ---------------- launch ----------------
extern "C" void kernel_launch(void* const* d_in, const int* in_sizes, int n_in,
                              void* d_out, int out_size) {
    const float* x        = (const float*)d_in[0];
    const float* memory   = (const float*)d_in[1];
    const float* link     = (const float*)d_in[2];
    const float* prec     = (const float*)d_in[3];
    const float* rw_old   = (const float*)d_in[4];
    const float* wwts     = (const float*)d_in[5];
    const float* usage_v  = (const float*)d_in[6];

    WPtrs p;
    for (int s = 0; s < 10; s++) {
        p.W[s]   = (const float*)d_in[7 + 2 * s];
        p.bia[s] = (const float*)d_in[8 + 2 * s];
    }
    float* out = (float*)d_out;

    k1_gemm<<<dim3(NPAD / 64, Bc / 64, KSPL), dim3(16, 16)>>>(x, p);
    k1r_act<<<(Bc * NOUT + 255) / 256, 256>>>(p);
    k34<<<K4BLKS + Bc, 512>>>(usage_v, wwts, rw_old, memory);
    k567<<<Bc, 512>>>();
    k8_link<<<dim3(NCH, Bc), 256>>>(link, prec, rw_old);
    k9_out<<<dim3(NCH, Bc), 512>>>(memory);
    k10_reduce<<<(Bc * Rc * Wc + 255) / 256, 256>>>(out);
}